// round 17
// baseline (speedup 1.0000x reference)
#include <cuda_runtime.h>
#include <math.h>
#include <stdint.h>

#define R_TOT 16384
#define WD 768
#define NHEADS 12
#define HDIM 64
#define NMB 256
#define MB 16
#define SEQ 4096
#define NB 4
#define LN_EPS 1e-6f

typedef unsigned long long u64;

// ---------------- scratch (device globals; no allocation allowed) -------------
__device__ float g_xqk [R_TOT * WD];                 // hidden@wq, later reused as G
__device__ float g_xv  [R_TOT * WD];                 // hidden@wv
__device__ float g_gate[R_TOT * WD];                 // hidden@wg (pre-gelu)
__device__ float g_XQ  [NB * NHEADS * NMB * MB * HDIM];
__device__ float g_XK  [NB * NHEADS * NMB * MB * HDIM];
__device__ float g_XVr [NB * NHEADS * NMB * MB * HDIM];
__device__ float g_lr  [NB * NHEADS * NMB * MB];
__device__ float g_scan[R_TOT * WD];

// ============ split-tf32 tensor-core GEMM (exact R6 kernel — known best) ======

__device__ __forceinline__ void split_tf32(float x, uint32_t& hi, uint32_t& lo) {
    float h;
    asm("cvt.rna.tf32.f32 %0, %1;" : "=f"(h) : "f"(x));
    float l = x - h;
    float l2;
    asm("cvt.rna.tf32.f32 %0, %1;" : "=f"(l2) : "f"(l));
    hi = __float_as_uint(h);
    lo = __float_as_uint(l2);
}

__device__ __forceinline__ void mma_tf32(float* c, const uint32_t* a, const uint32_t* b) {
    asm volatile(
        "mma.sync.aligned.m16n8k8.row.col.f32.tf32.tf32.f32 "
        "{%0,%1,%2,%3}, {%4,%5,%6,%7}, {%8,%9}, {%0,%1,%2,%3};"
        : "+f"(c[0]), "+f"(c[1]), "+f"(c[2]), "+f"(c[3])
        : "r"(a[0]), "r"(a[1]), "r"(a[2]), "r"(a[3]), "r"(b[0]), "r"(b[1]));
}

#define CP16(smem_u32, gptr) \
    asm volatile("cp.async.cg.shared.global [%0], [%1], 16;" :: "r"(smem_u32), "l"(gptr))

#define SA_STRIDE 20
#define SB_STRIDE 136

__global__ __launch_bounds__(256) void gemm_tf32_kernel(
    const float* __restrict__ A, const float* __restrict__ B,
    float* __restrict__ C, int M, int N, int K)
{
    __shared__ float sA[2][128 * SA_STRIDE];
    __shared__ float sB[2][16 * SB_STRIDE];

    const int tid  = threadIdx.x;
    const int wid  = tid >> 5;
    const int lane = tid & 31;
    const int lr   = lane >> 2;
    const int lc   = lane & 3;
    const int warpM = wid >> 2;
    const int warpN = wid & 3;

    const int NT = K / 16;

    const float* Ab = A + (size_t)(blockIdx.y * 128) * K;
    const float* Bb = B + blockIdx.x * 128;

    uint32_t sA_u32 = (uint32_t)__cvta_generic_to_shared(&sA[0][0]);
    uint32_t sB_u32 = (uint32_t)__cvta_generic_to_shared(&sB[0][0]);

    const int aRow0 = tid >> 2;
    const int aC4   = (tid & 3) * 4;
    const int bRow0 = tid >> 5;
    const int bC4   = (tid & 31) * 4;

    float acc[4][4][4];
#pragma unroll
    for (int m = 0; m < 4; m++)
#pragma unroll
        for (int n = 0; n < 4; n++)
#pragma unroll
            for (int e = 0; e < 4; e++) acc[m][n][e] = 0.f;

    {
        const float* ag = Ab + (size_t)aRow0 * K + aC4;
        CP16(sA_u32 + (aRow0 * SA_STRIDE + aC4) * 4, ag);
        CP16(sA_u32 + ((aRow0 + 64) * SA_STRIDE + aC4) * 4, ag + (size_t)64 * K);
        const float* bg = Bb + (size_t)bRow0 * N + bC4;
        CP16(sB_u32 + (bRow0 * SB_STRIDE + bC4) * 4, bg);
        CP16(sB_u32 + ((bRow0 + 8) * SB_STRIDE + bC4) * 4, bg + (size_t)8 * N);
        asm volatile("cp.async.commit_group;");
    }

    for (int kt = 0; kt < NT; kt++) {
        const int cur = kt & 1;
        if (kt + 1 < NT) {
            const int nxt = (kt + 1) & 1;
            uint32_t sAn = sA_u32 + nxt * 128 * SA_STRIDE * 4;
            uint32_t sBn = sB_u32 + nxt * 16 * SB_STRIDE * 4;
            const float* ag = Ab + (size_t)aRow0 * K + (kt + 1) * 16 + aC4;
            CP16(sAn + (aRow0 * SA_STRIDE + aC4) * 4, ag);
            CP16(sAn + ((aRow0 + 64) * SA_STRIDE + aC4) * 4, ag + (size_t)64 * K);
            const float* bg = Bb + (size_t)((kt + 1) * 16 + bRow0) * N + bC4;
            CP16(sBn + (bRow0 * SB_STRIDE + bC4) * 4, bg);
            CP16(sBn + ((bRow0 + 8) * SB_STRIDE + bC4) * 4, bg + (size_t)8 * N);
            asm volatile("cp.async.commit_group;");
            asm volatile("cp.async.wait_group 1;");
        } else {
            asm volatile("cp.async.wait_group 0;");
        }
        __syncthreads();

        const float* cA = &sA[cur][0];
        const float* cB = &sB[cur][0];
#pragma unroll
        for (int ks = 0; ks < 2; ks++) {
            uint32_t ahi[4][4], alo[4][4];
#pragma unroll
            for (int m = 0; m < 4; m++) {
                int r0 = warpM * 64 + m * 16 + lr;
                int c0 = ks * 8 + lc;
                split_tf32(cA[r0 * SA_STRIDE + c0],            ahi[m][0], alo[m][0]);
                split_tf32(cA[(r0 + 8) * SA_STRIDE + c0],      ahi[m][1], alo[m][1]);
                split_tf32(cA[r0 * SA_STRIDE + c0 + 4],        ahi[m][2], alo[m][2]);
                split_tf32(cA[(r0 + 8) * SA_STRIDE + c0 + 4],  ahi[m][3], alo[m][3]);
            }
            uint32_t bhi[4][2], blo[4][2];
#pragma unroll
            for (int n = 0; n < 4; n++) {
                int cc = warpN * 32 + n * 8 + lr;
                int r0 = ks * 8 + lc;
                split_tf32(cB[r0 * SB_STRIDE + cc],       bhi[n][0], blo[n][0]);
                split_tf32(cB[(r0 + 4) * SB_STRIDE + cc], bhi[n][1], blo[n][1]);
            }
#pragma unroll
            for (int m = 0; m < 4; m++)
#pragma unroll
                for (int n = 0; n < 4; n++) {
                    mma_tf32(acc[m][n], ahi[m], bhi[n]);
                    mma_tf32(acc[m][n], ahi[m], blo[n]);
                    mma_tf32(acc[m][n], alo[m], bhi[n]);
                }
        }
        __syncthreads();
    }

#pragma unroll
    for (int m = 0; m < 4; m++) {
        int row = blockIdx.y * 128 + warpM * 64 + m * 16 + lr;
#pragma unroll
        for (int n = 0; n < 4; n++) {
            int col = blockIdx.x * 128 + warpN * 32 + n * 8 + 2 * lc;
            float* cp = C + (size_t)row * N + col;
            *(float2*)cp = make_float2(acc[m][n][0], acc[m][n][1]);
            *(float2*)(cp + (size_t)8 * N) = make_float2(acc[m][n][2], acc[m][n][3]);
        }
    }
}

// ---------------- ttt_lr ------------------------------------------------------
__global__ __launch_bounds__(256) void lr_kernel(
    const float* __restrict__ hidden, const float* __restrict__ lrk,
    const float* __restrict__ lrb, float* __restrict__ out)
{
    int row = blockIdx.x * 8 + (threadIdx.x >> 5);
    int lane = threadIdx.x & 31;
    if (row >= R_TOT) return;
    const float* hr = hidden + (size_t)row * WD;
    float acc[NHEADS];
#pragma unroll
    for (int h = 0; h < NHEADS; h++) acc[h] = 0.f;
    for (int w = lane; w < WD; w += 32) {
        float hv = hr[w];
#pragma unroll
        for (int h = 0; h < NHEADS; h++) acc[h] += hv * lrk[h * WD + w];
    }
#pragma unroll
    for (int h = 0; h < NHEADS; h++) {
#pragma unroll
        for (int o = 16; o > 0; o >>= 1)
            acc[h] += __shfl_xor_sync(0xffffffffu, acc[h], o);
    }
    if (lane < NHEADS) {
        float x = acc[lane] + lrb[lane];
        float v = (1.0f / (1.0f + expf(-x))) * (1.0f / 64.0f);
        int b = row >> 12;
        int n = row & 4095;
        int nm = n >> 4, m = n & 15;
        out[(((size_t)b * NHEADS + lane) * NMB + nm) * MB + m] = v;
    }
}

// ---------------- causal dwconv(width 4) + RoPE + reorder ---------------------
__global__ __launch_bounds__(256) void convrope_kernel(
    const float* __restrict__ xqk, const float* __restrict__ xv,
    const float* __restrict__ kq, const float* __restrict__ bq,
    const float* __restrict__ kk, const float* __restrict__ bk,
    float* __restrict__ XQr, float* __restrict__ XKr, float* __restrict__ XVr)
{
    int idx = blockIdx.x * blockDim.x + threadIdx.x;
    if (idx >= R_TOT * 384) return;
    int c2 = idx % 384;
    int row = idx / 384;
    int c = c2 * 2;
    int n = row & 4095;
    int b = row >> 12;

    float q0 = bq[c], q1 = bq[c + 1];
    float k0 = bk[c], k1 = bk[c + 1];
#pragma unroll
    for (int t = 0; t < 4; t++) {
        int nn = n - 3 + t;
        if (nn >= 0) {
            const float* xr = xqk + ((size_t)(b * SEQ + nn)) * WD + c;
            float x0 = xr[0], x1 = xr[1];
            q0 += kq[t * WD + c] * x0;     q1 += kq[t * WD + c + 1] * x1;
            k0 += kk[t * WD + c] * x0;     k1 += kk[t * WD + c + 1] * x1;
        }
    }
    int h = c >> 6;
    int d = c & 63;
    int fi = d >> 1;
    int pos = n & 15;
    float freq = exp2f(-((float)(2 * fi) * (1.0f / 64.0f)) * 13.2877123795f);
    float ang = (float)pos * freq;
    float cs = cosf(ang), sn = sinf(ang);

    float qe = q0 * cs - q1 * sn;
    float qo = q0 * sn + q1 * cs;
    float ke = k0 * cs - k1 * sn;
    float ko = k0 * sn + k1 * cs;

    int nm = n >> 4, m = n & 15;
    size_t off = ((((size_t)b * NHEADS + h) * NMB + nm) * MB + m) * HDIM + d;
    XQr[off] = qe;  XQr[off + 1] = qo;
    XKr[off] = ke;  XKr[off + 1] = ko;
    const float* xvp = xv + (size_t)row * WD + c;
    XVr[off] = xvp[0];  XVr[off + 1] = xvp[1];
}

// ---------------- the TTT scan: FFMA2 (f32x2) version -------------------------
#define XS 68   // XQ/XK tile row stride (floats)

#define FMA2(acc, a, b) asm("fma.rn.f32x2 %0, %1, %2, %0;" : "+l"(acc) : "l"(a), "l"(b))
#define MUL2(d, a, b)   asm("mul.rn.f32x2 %0, %1, %2;" : "=l"(d) : "l"(a), "l"(b))
#define PACKD(d, x)     asm("mov.b64 %0, {%1, %1};" : "=l"(d) : "f"(x))
#define UNPK(lo, hi, v) asm("mov.b64 {%0, %1}, %2;" : "=f"(lo), "=f"(hi) : "l"(v))

__global__ __launch_bounds__(256) void scan_kernel(
    const float* __restrict__ W1g, const float* __restrict__ b1g,
    const float* __restrict__ glng, const float* __restrict__ blng,
    const float* __restrict__ lti,
    const float* __restrict__ XQg, const float* __restrict__ XKg,
    const float* __restrict__ XVg, const float* __restrict__ lrg,
    float* __restrict__ scan_out)
{
    __shared__ float W1s[64 * 64];
    __shared__ float b1s[64];
    __shared__ float XQs[16 * XS];
    __shared__ float XKs[16 * XS];
    __shared__ float XQd[16 * 128];    // duplicated (x,x) pairs
    __shared__ float XKd[16 * 128];
    __shared__ float grads[16 * 64];
    __shared__ float Attns[16 * 17];
    __shared__ float lrs[16];
    __shared__ float tis[16];
    __shared__ float gln[64], bln[64];

    const int bh = blockIdx.x;
    const int h = bh % NHEADS;
    const int b = bh / NHEADS;
    const int t = threadIdx.x;

    {
        const float* w1p = W1g + (size_t)h * 64 * 64;
        for (int j = t; j < 4096; j += 256) W1s[j] = w1p[j];
        if (t < 64) {
            b1s[t] = b1g[h * 64 + t];
            gln[t] = glng[h * 64 + t];
            bln[t] = blng[h * 64 + t];
        }
        if (t < 16) tis[t] = fmaxf(1.0f / (float)(t + 1) + lti[t], 0.0f);
    }
    __syncthreads();

    const int i  = t >> 4;
    const int cg = t & 15;
    const int d0 = cg * 4;

    const float gv0 = gln[d0], gv1 = gln[d0 + 1], gv2 = gln[d0 + 2], gv3 = gln[d0 + 3];
    const float bv0 = bln[d0], bv1 = bln[d0 + 1], bv2 = bln[d0 + 2], bv3 = bln[d0 + 3];
    const float ti_i = tis[i];
    const float le15 = tis[15];

    const float* XQb = XQg + (size_t)bh * NMB * MB * HDIM;
    const float* XKb = XKg + (size_t)bh * NMB * MB * HDIM;
    const float* XVb = XVg + (size_t)bh * NMB * MB * HDIM;
    const float* lrbp = lrg + (size_t)bh * NMB * MB;
    float* outb = scan_out + (size_t)b * SEQ * WD + h * HDIM;

    size_t tb = (size_t)i * HDIM + d0;
    float4 q4 = *(const float4*)(XQb + tb);
    float4 k4 = *(const float4*)(XKb + tb);
    float4 v4 = *(const float4*)(XVb + tb);
    float lrv = (t < 16) ? lrbp[t] : 0.f;

    for (int s = 0; s < NMB; s++) {
        // ---- stage tiles (normal + duplicated) ----
        *(float4*)&XQs[i * XS + d0] = q4;
        *(float4*)&XKs[i * XS + d0] = k4;
        *(float4*)&XQd[i * 128 + 2 * d0]     = make_float4(q4.x, q4.x, q4.y, q4.y);
        *(float4*)&XQd[i * 128 + 2 * d0 + 4] = make_float4(q4.z, q4.z, q4.w, q4.w);
        *(float4*)&XKd[i * 128 + 2 * d0]     = make_float4(k4.x, k4.x, k4.y, k4.y);
        *(float4*)&XKd[i * 128 + 2 * d0 + 4] = make_float4(k4.z, k4.z, k4.w, k4.w);
        if (t < 16) lrs[t] = lrv;
        __syncthreads();                               // A

        // ---- prefetch next mini-batch ----
        float4 q4n, k4n, v4n; float lrvn = 0.f;
        if (s + 1 < NMB) {
            size_t tb2 = (size_t)(s + 1) * MB * HDIM + i * HDIM + d0;
            q4n = *(const float4*)(XQb + tb2);
            k4n = *(const float4*)(XKb + tb2);
            v4n = *(const float4*)(XVb + tb2);
            if (t < 16) lrvn = lrbp[(s + 1) * MB + t];
        }

        // ---- phase 1: Z = XK@W1+b1, A = XQ@W1+b1, Attn = XQ@XK^T (f32x2) ----
        ulonglong2 b2 = *(const ulonglong2*)&b1s[d0];
        u64 Z01 = b2.x, Z23 = b2.y, A01 = b2.x, A23 = b2.y;
        u64 AT2 = 0ull;
#pragma unroll
        for (int k0 = 0; k0 < 64; k0 += 4) {
            ulonglong2 xkd1 = *(const ulonglong2*)&XKd[i * 128 + 2 * k0];
            ulonglong2 xkd2 = *(const ulonglong2*)&XKd[i * 128 + 2 * k0 + 4];
            ulonglong2 xqd1 = *(const ulonglong2*)&XQd[i * 128 + 2 * k0];
            ulonglong2 xqd2 = *(const ulonglong2*)&XQd[i * 128 + 2 * k0 + 4];
            ulonglong2 q2  = *(const ulonglong2*)&XQs[i * XS + k0];
            ulonglong2 ka2 = *(const ulonglong2*)&XKs[cg * XS + k0];
            FMA2(AT2, q2.x, ka2.x);
            FMA2(AT2, q2.y, ka2.y);
            {
                ulonglong2 w = *(const ulonglong2*)&W1s[(k0 + 0) * 64 + d0];
                FMA2(Z01, xkd1.x, w.x); FMA2(Z23, xkd1.x, w.y);
                FMA2(A01, xqd1.x, w.x); FMA2(A23, xqd1.x, w.y);
            }
            {
                ulonglong2 w = *(const ulonglong2*)&W1s[(k0 + 1) * 64 + d0];
                FMA2(Z01, xkd1.y, w.x); FMA2(Z23, xkd1.y, w.y);
                FMA2(A01, xqd1.y, w.x); FMA2(A23, xqd1.y, w.y);
            }
            {
                ulonglong2 w = *(const ulonglong2*)&W1s[(k0 + 2) * 64 + d0];
                FMA2(Z01, xkd2.x, w.x); FMA2(Z23, xkd2.x, w.y);
                FMA2(A01, xqd2.x, w.x); FMA2(A23, xqd2.x, w.y);
            }
            {
                ulonglong2 w = *(const ulonglong2*)&W1s[(k0 + 3) * 64 + d0];
                FMA2(Z01, xkd2.y, w.x); FMA2(Z23, xkd2.y, w.y);
                FMA2(A01, xqd2.y, w.x); FMA2(A23, xqd2.y, w.y);
            }
        }
        {
            float atl, ath;
            UNPK(atl, ath, AT2);
            Attns[i * 17 + cg] = atl + ath;
        }
        float zx, zy, zz, zw;
        UNPK(zx, zy, Z01);
        UNPK(zz, zw, Z23);

        // ---- grad = ln_fused_l2_bwd(Z1, XV-XK) ----
        float sum = zx + zy + zz + zw;
        sum += __shfl_xor_sync(0xffffffffu, sum, 1);
        sum += __shfl_xor_sync(0xffffffffu, sum, 2);
        sum += __shfl_xor_sync(0xffffffffu, sum, 4);
        sum += __shfl_xor_sync(0xffffffffu, sum, 8);
        float mu = sum * (1.0f / 64.0f);
        float cx = zx - mu, cy = zy - mu, cz = zz - mu, cw = zw - mu;
        float s2 = cx * cx + cy * cy + cz * cz + cw * cw;
        s2 += __shfl_xor_sync(0xffffffffu, s2, 1);
        s2 += __shfl_xor_sync(0xffffffffu, s2, 2);
        s2 += __shfl_xor_sync(0xffffffffu, s2, 4);
        s2 += __shfl_xor_sync(0xffffffffu, s2, 8);
        float istd = 1.0f / sqrtf(s2 * (1.0f / 64.0f) + LN_EPS);
        float xh0 = cx * istd, xh1 = cy * istd, xh2 = cz * istd, xh3 = cw * istd;
        // T = XV - XK straight from this thread's registers (same row/cols)
        float t0 = v4.x - k4.x, t1 = v4.y - k4.y, t2 = v4.z - k4.z, t3 = v4.w - k4.w;
        float g0 = (gv0 * xh0 + bv0 - t0) * gv0;
        float g1 = (gv1 * xh1 + bv1 - t1) * gv1;
        float g2 = (gv2 * xh2 + bv2 - t2) * gv2;
        float g3 = (gv3 * xh3 + bv3 - t3) * gv3;
        float sg = g0 + g1 + g2 + g3;
        sg += __shfl_xor_sync(0xffffffffu, sg, 1);
        sg += __shfl_xor_sync(0xffffffffu, sg, 2);
        sg += __shfl_xor_sync(0xffffffffu, sg, 4);
        sg += __shfl_xor_sync(0xffffffffu, sg, 8);
        float sgx = g0 * xh0 + g1 * xh1 + g2 * xh2 + g3 * xh3;
        sgx += __shfl_xor_sync(0xffffffffu, sgx, 1);
        sgx += __shfl_xor_sync(0xffffffffu, sgx, 2);
        sgx += __shfl_xor_sync(0xffffffffu, sgx, 4);
        sgx += __shfl_xor_sync(0xffffffffu, sgx, 8);
        float cf = istd * (1.0f / 64.0f);
        *(float4*)&grads[i * 64 + d0] = make_float4(
            (64.f * g0 - sg - xh0 * sgx) * cf,
            (64.f * g1 - sg - xh1 * sgx) * cf,
            (64.f * g2 - sg - xh2 * sgx) * cf,
            (64.f * g3 - sg - xh3 * sgx) * cf);
        __syncthreads();                               // B

        // ---- phase 2a: A -= sum_{j<=i} eta(i,j)*(Attn+1)*grad[j]  (f32x2) ----
        for (int jj = 0; jj <= i; jj++) {
            float c = ti_i * lrs[jj] * (Attns[i * 17 + jj] + 1.0f);
            u64 C2;
            PACKD(C2, -c);
            ulonglong2 gr = *(const ulonglong2*)&grads[jj * 64 + d0];
            FMA2(A01, C2, gr.x);
            FMA2(A23, C2, gr.y);
        }
        float ax, ay, az, aw;
        UNPK(ax, ay, A01);
        UNPK(az, aw, A23);

        // ---- out = XQ + ln_fwd(Z1_bar) ----
        float su = ax + ay + az + aw;
        su += __shfl_xor_sync(0xffffffffu, su, 1);
        su += __shfl_xor_sync(0xffffffffu, su, 2);
        su += __shfl_xor_sync(0xffffffffu, su, 4);
        su += __shfl_xor_sync(0xffffffffu, su, 8);
        float mu2 = su * (1.0f / 64.0f);
        float ex = ax - mu2, ey = ay - mu2, ez = az - mu2, ew = aw - mu2;
        float v2 = ex * ex + ey * ey + ez * ez + ew * ew;
        v2 += __shfl_xor_sync(0xffffffffu, v2, 1);
        v2 += __shfl_xor_sync(0xffffffffu, v2, 2);
        v2 += __shfl_xor_sync(0xffffffffu, v2, 4);
        v2 += __shfl_xor_sync(0xffffffffu, v2, 8);
        float istd2 = 1.0f / sqrtf(v2 * (1.0f / 64.0f) + LN_EPS);
        *(float4*)(outb + (size_t)(s * MB + i) * WD + d0) = make_float4(
            q4.x + gv0 * (ex * istd2) + bv0,
            q4.y + gv1 * (ey * istd2) + bv1,
            q4.z + gv2 * (ez * istd2) + bv2,
            q4.w + gv3 * (ew * istd2) + bv3);

        // ---- phase 2b: W1[4i..4i+3][d0..d0+3] -= (le*XK)^T@grad  (f32x2) ----
        {
            ulonglong2 wa0 = *(const ulonglong2*)&W1s[(4 * i + 0) * 64 + d0];
            ulonglong2 wa1 = *(const ulonglong2*)&W1s[(4 * i + 1) * 64 + d0];
            ulonglong2 wa2 = *(const ulonglong2*)&W1s[(4 * i + 2) * 64 + d0];
            ulonglong2 wa3 = *(const ulonglong2*)&W1s[(4 * i + 3) * 64 + d0];
#pragma unroll
            for (int ii = 0; ii < 16; ii++) {
                float nlg = -(le15 * lrs[ii]);
                u64 NL2;
                PACKD(NL2, nlg);
                ulonglong2 xd1 = *(const ulonglong2*)&XKd[ii * 128 + 2 * (4 * i)];
                ulonglong2 xd2 = *(const ulonglong2*)&XKd[ii * 128 + 2 * (4 * i) + 4];
                u64 C0, C1, C2_, C3;
                MUL2(C0,  NL2, xd1.x);
                MUL2(C1,  NL2, xd1.y);
                MUL2(C2_, NL2, xd2.x);
                MUL2(C3,  NL2, xd2.y);
                ulonglong2 gr = *(const ulonglong2*)&grads[ii * 64 + d0];
                FMA2(wa0.x, C0,  gr.x); FMA2(wa0.y, C0,  gr.y);
                FMA2(wa1.x, C1,  gr.x); FMA2(wa1.y, C1,  gr.y);
                FMA2(wa2.x, C2_, gr.x); FMA2(wa2.y, C2_, gr.y);
                FMA2(wa3.x, C3,  gr.x); FMA2(wa3.y, C3,  gr.y);
            }
            *(ulonglong2*)&W1s[(4 * i + 0) * 64 + d0] = wa0;
            *(ulonglong2*)&W1s[(4 * i + 1) * 64 + d0] = wa1;
            *(ulonglong2*)&W1s[(4 * i + 2) * 64 + d0] = wa2;
            *(ulonglong2*)&W1s[(4 * i + 3) * 64 + d0] = wa3;
        }
        // ---- b1 update (threads i==0) ----
        if (i == 0) {
            float4 bb = *(const float4*)&b1s[d0];
#pragma unroll
            for (int ii = 0; ii < 16; ii++) {
                float lg = le15 * lrs[ii];
                float4 gr = *(const float4*)&grads[ii * 64 + d0];
                bb.x -= lg * gr.x; bb.y -= lg * gr.y; bb.z -= lg * gr.z; bb.w -= lg * gr.w;
            }
            *(float4*)&b1s[d0] = bb;
        }

        q4 = q4n; k4 = k4n; v4 = v4n; lrv = lrvn;
        __syncthreads();                               // C
    }
}

// ---------------- post-norm + gelu gate -> G ---------------------------------
__global__ __launch_bounds__(256) void combine_kernel(
    const float* __restrict__ pns, const float* __restrict__ pnb,
    const float* __restrict__ scan_in, const float* __restrict__ gatef,
    float* __restrict__ G)
{
    __shared__ float red[16];
    __shared__ float muv, istdv;
    int row = blockIdx.x;
    int t = threadIdx.x;
    const float* x = scan_in + (size_t)row * WD;
    float v0 = x[t], v1 = x[t + 256], v2 = x[t + 512];
    float s = v0 + v1 + v2;
    float s2 = v0 * v0 + v1 * v1 + v2 * v2;
#pragma unroll
    for (int o = 16; o > 0; o >>= 1) {
        s  += __shfl_xor_sync(0xffffffffu, s, o);
        s2 += __shfl_xor_sync(0xffffffffu, s2, o);
    }
    if ((t & 31) == 0) { red[t >> 5] = s; red[8 + (t >> 5)] = s2; }
    __syncthreads();
    if (t == 0) {
        float a = 0.f, b2 = 0.f;
        for (int j = 0; j < 8; j++) { a += red[j]; b2 += red[8 + j]; }
        float mu = a * (1.0f / 768.0f);
        float var = b2 * (1.0f / 768.0f) - mu * mu;
        muv = mu;
        istdv = 1.0f / sqrtf(var + LN_EPS);
    }
    __syncthreads();
    float mu = muv, istd = istdv;
    const float* gp = gatef + (size_t)row * WD;
    float* Gp = G + (size_t)row * WD;
    float vv[3] = {v0, v1, v2};
#pragma unroll
    for (int j = 0; j < 3; j++) {
        int c = t + j * 256;
        float z = pns[c] * ((vv[j] - mu) * istd) + pnb[c];
        float gx = gp[c];
        float inner = 0.7978845608028654f * (gx + 0.044715f * gx * gx * gx);
        float gl = 0.5f * gx * (1.0f + tanhf(inner));
        Gp[c] = gl * z;
    }
}

// ---------------- launch: fork-join overlap (R16 schedule) --------------------
extern "C" void kernel_launch(void* const* d_in, const int* in_sizes, int n_in,
                              void* d_out, int out_size)
{
    const float* hidden = (const float*)d_in[0];
    const float* wq  = (const float*)d_in[1];
    const float* wv  = (const float*)d_in[2];
    const float* wo  = (const float*)d_in[3];
    const float* wg  = (const float*)d_in[4];
    const float* ckq = (const float*)d_in[5];
    const float* cbq = (const float*)d_in[6];
    const float* ckk = (const float*)d_in[7];
    const float* cbk = (const float*)d_in[8];
    const float* W1  = (const float*)d_in[9];
    const float* b1  = (const float*)d_in[10];
    const float* nsc = (const float*)d_in[11];
    const float* nbi = (const float*)d_in[12];
    const float* lrk = (const float*)d_in[13];
    const float* lrb = (const float*)d_in[14];
    const float* lti = (const float*)d_in[15];
    const float* pns = (const float*)d_in[16];
    const float* pnb = (const float*)d_in[17];
    float* out = (float*)d_out;

    float *xqk, *xv, *gate, *XQ, *XK, *XVr, *lr, *scan;
    cudaGetSymbolAddress((void**)&xqk,  g_xqk);
    cudaGetSymbolAddress((void**)&xv,   g_xv);
    cudaGetSymbolAddress((void**)&gate, g_gate);
    cudaGetSymbolAddress((void**)&XQ,   g_XQ);
    cudaGetSymbolAddress((void**)&XK,   g_XK);
    cudaGetSymbolAddress((void**)&XVr,  g_XVr);
    cudaGetSymbolAddress((void**)&lr,   g_lr);
    cudaGetSymbolAddress((void**)&scan, g_scan);

    static cudaStream_t s1;
    static cudaEvent_t evRoot, evLr, evConv, evGate;
    static int init = 0;
    if (!init) {
        cudaStreamCreateWithFlags(&s1, cudaStreamNonBlocking);
        cudaEventCreateWithFlags(&evRoot, cudaEventDisableTiming);
        cudaEventCreateWithFlags(&evLr,   cudaEventDisableTiming);
        cudaEventCreateWithFlags(&evConv, cudaEventDisableTiming);
        cudaEventCreateWithFlags(&evGate, cudaEventDisableTiming);
        init = 1;
    }

    dim3 gg(WD / 128, R_TOT / 128);

    // fork side stream
    cudaEventRecord(evRoot, 0);
    cudaStreamWaitEvent(s1, evRoot, 0);

    // s1: lr (needs only hidden) — runs under the wq GEMM
    lr_kernel<<<R_TOT / 8, 256, 0, s1>>>(hidden, lrk, lrb, lr);
    cudaEventRecord(evLr, s1);

    // s0: the two GEMMs feeding convrope
    gemm_tf32_kernel<<<gg, 256>>>(hidden, wq, xqk, R_TOT, WD, WD);
    gemm_tf32_kernel<<<gg, 256>>>(hidden, wv, xv, R_TOT, WD, WD);
    convrope_kernel<<<(R_TOT * 384 + 255) / 256, 256>>>(xqk, xv, ckq, cbq, ckk, cbk, XQ, XK, XVr);
    cudaEventRecord(evConv, 0);

    // s0: scan needs lr results
    cudaStreamWaitEvent(0, evLr, 0);
    scan_kernel<<<NB * NHEADS, 256>>>(W1, b1, nsc, nbi, lti, XQ, XK, XVr, lr, scan);

    // s1: wg GEMM gated to start when the scan starts — hides under it
    cudaStreamWaitEvent(s1, evConv, 0);
    gemm_tf32_kernel<<<gg, 256, 0, s1>>>(hidden, wg, gate, R_TOT, WD, WD);
    cudaEventRecord(evGate, s1);

    // s0: join — combine needs gate
    cudaStreamWaitEvent(0, evGate, 0);
    combine_kernel<<<R_TOT, 256>>>(pns, pnb, scan, gate, xqk);
    gemm_tf32_kernel<<<gg, 256>>>(xqk, wo, out, R_TOT, WD, WD);
}